// round 7
// baseline (speedup 1.0000x reference)
#include <cuda_runtime.h>
#include <math.h>

#define MAXN 20480
#define MAXE 122880
#define NPLANE ((size_t)MAXN * 64)
#define EPLANE ((size_t)MAXE * 64)

// ---------------- scratch (__device__, static) ----------------
// node side
__device__ float g_sn  [MAXN * 64];        // scalars of node_attr
__device__ float g_xv  [3 * MAXN * 64];    // vector planes of node_attr
__device__ float g_f0n [MAXN * 128];       // [s, |v|]
__device__ float g_t1  [MAXN * 128];
__device__ float g_g   [MAXN * 128];       // norm_gate MLP out
__device__ float g_hvg [3 * MAXN * 64];    // gated vectors
__device__ float g_na0s[MAXN * 64];
__device__ float g_na0v[3 * MAXN * 64];
__device__ float g_hs  [MAXN * 64];
__device__ float g_hv  [3 * MAXN * 64];
// edge side
__device__ float g_s0  [(size_t)MAXE * 192];
__device__ float g_t8  [(size_t)MAXE * 8];
__device__ float g_u   [(size_t)MAXE * 64];
__device__ float g_fe  [(size_t)MAXE * 320];
__device__ float g_w   [(size_t)MAXE * 320];
__device__ float g_f0e [(size_t)MAXE * 128];
__device__ float g_pv  [3 * (size_t)MAXE * 64];
__device__ float g_t2  [(size_t)MAXE * 128];
__device__ float g_g2  [(size_t)MAXE * 128];
__device__ float g_vg  [3 * (size_t)MAXE * 64];

__device__ __forceinline__ float siluf(float x) { return x * (1.f / (1.f + __expf(-x))); }
__device__ __forceinline__ float sspf(float x) {
    float sp = (x > 20.f) ? x : log1pf(__expf(x));
    return sp - 0.6931471805599453f;
}

// packed fp32x2 FMA (sm_103a)
#define FFMA2(d, a, b) asm("fma.rn.f32x2 %0, %1, %2, %0;" : "+l"(d) : "l"(a), "l"(b))

// ---------------- generic tiled GEMM ----------------
// C[row, n] = epilogue( alpha * sum_k A[row,k] * W[k,n] )
// block tile: 128 rows x 64 cols, BK=32. 256 threads, thread tile 8x4 via f32x2 pairs.
#define BM 128
#define BN 64
#define BK 32
#define AS_LD 132   // padded, 16B-aligned rows
#define WS_LD 136   // duplicated-pair weight rows, 16B-aligned

__global__ void __launch_bounds__(256) gemm_kernel(
    const float* __restrict__ A, int lda, size_t aPlane,
    const float* __restrict__ W, int ldw,
    const float* __restrict__ bias,
    const float* __restrict__ aux, int auxLd, float auxScale,
    const float* __restrict__ res,
    float* __restrict__ out, int outLd, int colStride, int colOff, int zColStep, size_t outPlane,
    int M, int K, float alpha, int act)
{
    __shared__ __align__(16) float As[BK * AS_LD];
    __shared__ __align__(16) float WsD[BK * WS_LD];

    const int z = blockIdx.z;
    A += (size_t)z * aPlane;
    out += (size_t)z * outPlane;
    const int cOff = colOff + z * zColStep;

    const int tid = threadIdx.x;
    const int tx = tid & 15;       // col group: 4 cols
    const int ty = tid >> 4;       // row group: 8 rows
    const int wid = tid >> 5, lane = tid & 31;
    const int rowBase = blockIdx.x * BM;
    const int nBase = blockIdx.y * BN;

    unsigned long long acc[4][4];
#pragma unroll
    for (int p = 0; p < 4; p++)
#pragma unroll
        for (int c = 0; c < 4; c++) acc[p][c] = 0ull;

    for (int k0 = 0; k0 < K; k0 += BK) {
        // fill A tile: As[k][m], warp wid loads 16 rows, lane = k
#pragma unroll 4
        for (int r = 0; r < 16; r++) {
            int mLoc = wid * 16 + r;
            int gRow = rowBase + mLoc;
            float v = 0.f;
            if (gRow < M) v = A[(size_t)gRow * lda + k0 + lane];
            As[lane * AS_LD + mLoc] = v;
        }
        // fill duplicated W tile
        for (int i = tid; i < BK * BN; i += 256) {
            int k = i >> 6, n = i & 63;
            float wv = W[(size_t)(k0 + k) * ldw + nBase + n];
            int o = k * WS_LD + 2 * n;
            WsD[o] = wv; WsD[o + 1] = wv;
        }
        __syncthreads();

#pragma unroll
        for (int k = 0; k < BK; k++) {
            const ulonglong2* ap = (const ulonglong2*)&As[k * AS_LD + ty * 8];
            ulonglong2 a0 = ap[0], a1 = ap[1];                 // row pairs (0,1)(2,3)(4,5)(6,7)
            const ulonglong2* wp = (const ulonglong2*)&WsD[k * WS_LD + tx * 8];
            ulonglong2 w0 = wp[0], w1 = wp[1];                 // dup cols c0,c1,c2,c3
            FFMA2(acc[0][0], a0.x, w0.x); FFMA2(acc[0][1], a0.x, w0.y);
            FFMA2(acc[0][2], a0.x, w1.x); FFMA2(acc[0][3], a0.x, w1.y);
            FFMA2(acc[1][0], a0.y, w0.x); FFMA2(acc[1][1], a0.y, w0.y);
            FFMA2(acc[1][2], a0.y, w1.x); FFMA2(acc[1][3], a0.y, w1.y);
            FFMA2(acc[2][0], a1.x, w0.x); FFMA2(acc[2][1], a1.x, w0.y);
            FFMA2(acc[2][2], a1.x, w1.x); FFMA2(acc[2][3], a1.x, w1.y);
            FFMA2(acc[3][0], a1.y, w0.x); FFMA2(acc[3][1], a1.y, w0.y);
            FFMA2(acc[3][2], a1.y, w1.x); FFMA2(acc[3][3], a1.y, w1.y);
        }
        __syncthreads();
    }

    // epilogue
#pragma unroll
    for (int p = 0; p < 4; p++) {
#pragma unroll
        for (int h = 0; h < 2; h++) {
            int row = rowBase + ty * 8 + 2 * p + h;
            if (row >= M) continue;
#pragma unroll
            for (int c = 0; c < 4; c++) {
                unsigned long long uacc = acc[p][c];
                float v = __uint_as_float(h == 0 ? (unsigned)uacc : (unsigned)(uacc >> 32));
                v *= alpha;
                int nG = nBase + tx * 4 + c;
                if (bias) v += bias[nG];
                if (act == 1) v = siluf(v);
                if (aux) v *= aux[(size_t)row * auxLd + nG] * auxScale;
                size_t oi = (size_t)row * outLd + cOff + (size_t)nG * colStride;
                if (res) v += res[oi];
                out[oi] = v;
            }
        }
    }
}

// ---------------- elementwise / gather kernels ----------------

__global__ void prep_node_kernel(const float* __restrict__ na, int N) {
    int idx = blockIdx.x * blockDim.x + threadIdx.x;
    int n = idx >> 6, j = idx & 63;
    if (n >= N) return;
    const float* b = na + (size_t)n * 256;
    float s = b[j];
    g_sn[n * 64 + j] = s;
    g_f0n[n * 128 + j] = s;
    float nn = 0.f;
#pragma unroll
    for (int c = 0; c < 3; c++) {
        float x = b[64 + 3 * j + c];
        g_xv[(size_t)c * NPLANE + n * 64 + j] = x;
        nn += x * x;
    }
    g_f0n[n * 128 + 64 + j] = sqrtf(nn);
}

__global__ void gate_node_kernel(int N) {
    int idx = blockIdx.x * blockDim.x + threadIdx.x;
    int n = idx >> 6, j = idx & 63;
    if (n >= N) return;
    float ga = g_g[n * 128 + 64 + j];
#pragma unroll
    for (int c = 0; c < 3; c++)
        g_hvg[(size_t)c * NPLANE + n * 64 + j] = g_xv[(size_t)c * NPLANE + n * 64 + j] * ga;
}

// s0 = [na0_s[dst], na0_s[src], ip/3]; t8 = ssp(edge_attr @ feW1 / sqrt(32))
__global__ void gather_kernel(const float* __restrict__ ea, const int* __restrict__ ei,
                              const float* __restrict__ feW1, int E) {
    int idx = blockIdx.x * blockDim.x + threadIdx.x;
    int e = idx >> 6, j = idx & 63;
    if (e >= E) return;
    int dst = ei[e], src = ei[E + e];
    g_s0[(size_t)e * 192 + j] = g_na0s[dst * 64 + j];
    g_s0[(size_t)e * 192 + 64 + j] = g_na0s[src * 64 + j];
    float ip = 0.f;
#pragma unroll
    for (int c = 0; c < 3; c++)
        ip += g_na0v[(size_t)c * NPLANE + dst * 64 + j] * g_na0v[(size_t)c * NPLANE + src * 64 + j];
    g_s0[(size_t)e * 192 + 128 + j] = ip * (1.f / 3.f);
    if (j < 8) {
        float a = 0.f;
        const float* er = ea + (size_t)e * 32;
#pragma unroll 8
        for (int k = 0; k < 32; k++) a += er[k] * feW1[k * 8 + j];
        g_t8[(size_t)e * 8 + j] = sspf(a * 0.17677669529663687f);
    }
}

// fe = t8 @ feW2 (unscaled; scale folded into Q3 auxScale)
__global__ void fe_kernel(const float* __restrict__ feW2, int E) {
    int idx = blockIdx.x * blockDim.x + threadIdx.x;
    int e = idx / 80, q = idx % 80;
    if (e >= E) return;
    float t[8];
#pragma unroll
    for (int i = 0; i < 8; i++) t[i] = g_t8[(size_t)e * 8 + i];
    int n0 = q * 4;
    float4 acc = make_float4(0.f, 0.f, 0.f, 0.f);
#pragma unroll
    for (int i = 0; i < 8; i++) {
        float4 wv = *(const float4*)&feW2[i * 320 + n0];
        acc.x += t[i] * wv.x; acc.y += t[i] * wv.y; acc.z += t[i] * wv.z; acc.w += t[i] * wv.w;
    }
    *(float4*)&g_fe[(size_t)e * 320 + n0] = acc;
}

// tensor product: f0e = [pair_s, |pair_v|], pv planes
__global__ void tp_kernel(const int* __restrict__ ei, int E) {
    int idx = blockIdx.x * blockDim.x + threadIdx.x;
    int e = idx >> 4, t = idx & 15;
    if (e >= E) return;
    int dst = ei[e], src = ei[E + e];
    const float C0 = 0.4472135954999579f, C1 = 0.7745966692414834f;
    const float IS3 = 0.5773502691896258f, IS6 = 0.4082482904638630f;
    const float* we = g_w + (size_t)e * 320;
#pragma unroll
    for (int k = 0; k < 4; k++) {
        int i = 4 * t + k;
        float xs = g_hs[src * 64 + i], ys = g_hs[dst * 64 + i];
        float xv0 = g_hv[0 * NPLANE + src * 64 + i], yv0 = g_hv[0 * NPLANE + dst * 64 + i];
        float xv1 = g_hv[1 * NPLANE + src * 64 + i], yv1 = g_hv[1 * NPLANE + dst * 64 + i];
        float xv2 = g_hv[2 * NPLANE + src * 64 + i], yv2 = g_hv[2 * NPLANE + dst * 64 + i];
        float ipv = xv0 * yv0 + xv1 * yv1 + xv2 * yv2;
        float psv = C0 * (we[i] * xs * ys + we[192 + i] * ipv * IS3);
        float cx = xv1 * yv2 - xv2 * yv1;
        float cy = xv2 * yv0 - xv0 * yv2;
        float cz = xv0 * yv1 - xv1 * yv0;
        float a011 = we[64 + i] * IS3 * C1;
        float a101 = we[128 + i] * IS3 * C1;
        float a111 = we[256 + i] * IS6 * C1;
        float p0 = a011 * xs * yv0 + a101 * xv0 * ys + a111 * cx;
        float p1 = a011 * xs * yv1 + a101 * xv1 * ys + a111 * cy;
        float p2 = a011 * xs * yv2 + a101 * xv2 * ys + a111 * cz;
        g_pv[0 * EPLANE + (size_t)e * 64 + i] = p0;
        g_pv[1 * EPLANE + (size_t)e * 64 + i] = p1;
        g_pv[2 * EPLANE + (size_t)e * 64 + i] = p2;
        g_f0e[(size_t)e * 128 + i] = psv;
        g_f0e[(size_t)e * 128 + 64 + i] = sqrtf(p0 * p0 + p1 * p1 + p2 * p2);
    }
}

__global__ void gate_edge_kernel(int E) {
    int idx = blockIdx.x * blockDim.x + threadIdx.x;
    int e = idx >> 6, j = idx & 63;
    if (e >= E) return;
    float ga = g_g2[(size_t)e * 128 + 64 + j];
#pragma unroll
    for (int c = 0; c < 3; c++)
        g_vg[(size_t)c * EPLANE + (size_t)e * 64 + j] = g_pv[(size_t)c * EPLANE + (size_t)e * 64 + j] * ga;
}

// ---------------- host ----------------

static void launch_gemm(const float* A, int lda, size_t aPlane,
                        const float* W, int ldw, const float* bias,
                        const float* aux, int auxLd, float auxScale,
                        const float* res,
                        float* out, int outLd, int colStride, int colOff, int zColStep, size_t outPlane,
                        int M, int K, int N, int planes, float alpha, int act)
{
    dim3 grid((M + BM - 1) / BM, N / BN, planes);
    gemm_kernel<<<grid, 256>>>(A, lda, aPlane, W, ldw, bias, aux, auxLd, auxScale, res,
                               out, outLd, colStride, colOff, zColStep, outPlane, M, K, alpha, act);
}

extern "C" void kernel_launch(void* const* d_in, const int* in_sizes, int n_in,
                              void* d_out, int out_size)
{
    const float* node_attr = (const float*)d_in[0];
    const float* edge_attr = (const float*)d_in[1];
    const float* npa       = (const float*)d_in[2];
    const float* Wi0 = (const float*)d_in[3];
    const float* bi0 = (const float*)d_in[4];
    const float* Wi1 = (const float*)d_in[5];
    const float* gpW1 = (const float*)d_in[6];
    const float* gpb1 = (const float*)d_in[7];
    const float* gpW2 = (const float*)d_in[8];
    const float* gpb2 = (const float*)d_in[9];
    const float* Wn0 = (const float*)d_in[10];
    const float* bn0 = (const float*)d_in[11];
    const float* Wn1 = (const float*)d_in[12];
    const float* feW1 = (const float*)d_in[13];
    const float* feW2 = (const float*)d_in[14];
    const float* fsW1 = (const float*)d_in[15];
    const float* fsb1 = (const float*)d_in[16];
    const float* fsW2 = (const float*)d_in[17];
    const float* fsb2 = (const float*)d_in[18];
    const float* gW1 = (const float*)d_in[19];
    const float* gb1 = (const float*)d_in[20];
    const float* gW2 = (const float*)d_in[21];
    const float* gb2 = (const float*)d_in[22];
    const float* Wo0 = (const float*)d_in[23];
    const float* bo0 = (const float*)d_in[24];
    const float* Wo1 = (const float*)d_in[25];
    const int*   ei  = (const int*)d_in[26];

    int N = in_sizes[0] / 256; if (N > MAXN) N = MAXN;
    int E = in_sizes[26] / 2;  if (E > MAXE) E = MAXE;
    float* out = (float*)d_out;

    float *sn, *xv, *f0n, *t1, *gg, *hvg, *na0s, *na0v, *hs, *hv;
    float *s0, *u, *fe, *w, *f0e, *pv, *t2, *g2, *vg;
    cudaGetSymbolAddress((void**)&sn, g_sn);   cudaGetSymbolAddress((void**)&xv, g_xv);
    cudaGetSymbolAddress((void**)&f0n, g_f0n); cudaGetSymbolAddress((void**)&t1, g_t1);
    cudaGetSymbolAddress((void**)&gg, g_g);    cudaGetSymbolAddress((void**)&hvg, g_hvg);
    cudaGetSymbolAddress((void**)&na0s, g_na0s); cudaGetSymbolAddress((void**)&na0v, g_na0v);
    cudaGetSymbolAddress((void**)&hs, g_hs);   cudaGetSymbolAddress((void**)&hv, g_hv);
    cudaGetSymbolAddress((void**)&s0, g_s0);   cudaGetSymbolAddress((void**)&u, g_u);
    cudaGetSymbolAddress((void**)&fe, g_fe);   cudaGetSymbolAddress((void**)&w, g_w);
    cudaGetSymbolAddress((void**)&f0e, g_f0e); cudaGetSymbolAddress((void**)&pv, g_pv);
    cudaGetSymbolAddress((void**)&t2, g_t2);   cudaGetSymbolAddress((void**)&g2, g_g2);
    cudaGetSymbolAddress((void**)&vg, g_vg);

    const float ISQ8 = 0.3535533905932738f;

    // ---- node pipeline ----
    prep_node_kernel<<<(N * 64 + 255) / 256, 256>>>(node_attr, N);
    launch_gemm(sn, 64, 0, Wi0, 64, bi0, 0, 0, 0.f, 0,
                na0s, 64, 1, 0, 0, 0, N, 64, 64, 1, 0.125f, 0);
    launch_gemm(xv, 64, NPLANE, Wi1, 64, 0, 0, 0, 0.f, 0,
                na0v, 64, 1, 0, 0, NPLANE, N, 64, 64, 3, 0.125f, 0);
    launch_gemm(f0n, 128, 0, gpW1, 128, gpb1, 0, 0, 0.f, 0,
                t1, 128, 1, 0, 0, 0, N, 128, 128, 1, 1.f, 1);
    launch_gemm(t1, 128, 0, gpW2, 128, gpb2, 0, 0, 0.f, 0,
                gg, 128, 1, 0, 0, 0, N, 128, 128, 1, 1.f, 0);
    gate_node_kernel<<<(N * 64 + 255) / 256, 256>>>(N);
    launch_gemm(gg, 128, 0, Wn0, 64, bn0, 0, 0, 0.f, 0,
                hs, 64, 1, 0, 0, 0, N, 64, 64, 1, 0.125f, 0);
    launch_gemm(hvg, 64, NPLANE, Wn1, 64, 0, 0, 0, 0.f, 0,
                hv, 64, 1, 0, 0, NPLANE, N, 64, 64, 3, 0.125f, 0);

    // ---- edge pipeline ----
    gather_kernel<<<(E * 64 + 255) / 256, 256>>>(edge_attr, ei, feW1, E);
    launch_gemm(s0, 192, 0, fsW1, 64, fsb1, 0, 0, 0.f, 0,
                u, 64, 1, 0, 0, 0, E, 192, 64, 1, 1.f, 1);
    fe_kernel<<<(E * 80 + 255) / 256, 256>>>(feW2, E);
    launch_gemm(u, 64, 0, fsW2, 320, fsb2, fe, 320, ISQ8, 0,
                w, 320, 1, 0, 0, 0, E, 64, 320, 1, 1.f, 0);
    tp_kernel<<<(E * 16 + 255) / 256, 256>>>(ei, E);
    launch_gemm(f0e, 128, 0, gW1, 128, gb1, 0, 0, 0.f, 0,
                t2, 128, 1, 0, 0, 0, E, 128, 128, 1, 1.f, 1);
    launch_gemm(t2, 128, 0, gW2, 128, gb2, 0, 0, 0.f, 0,
                g2, 128, 1, 0, 0, 0, E, 128, 128, 1, 1.f, 0);
    gate_edge_kernel<<<(E * 64 + 255) / 256, 256>>>(E);
    // out scalars: cols 0..63
    launch_gemm(g2, 128, 0, Wo0, 64, bo0, 0, 0, 0.f, npa,
                out, 256, 1, 0, 0, 0, E, 64, 64, 1, 0.125f, 0);
    // out vectors: cols 64 + 3n + z
    launch_gemm(vg, 64, EPLANE, Wo1, 64, 0, 0, 0, 0.f, npa,
                out, 256, 3, 64, 1, 0, E, 64, 64, 3, 0.125f, 0);
}

// round 9
// speedup vs baseline: 1.5051x; 1.5051x over previous
#include <cuda_runtime.h>
#include <math.h>

#define MAXN 20480
#define MAXE 122880
#define NPLANE ((size_t)MAXN * 64)
#define EPLANE ((size_t)MAXE * 64)

// ---------------- scratch (__device__, static) ----------------
// node side
__device__ float g_sn  [MAXN * 64];        // scalars of node_attr
__device__ float g_xv  [3 * MAXN * 64];    // vector planes of node_attr
__device__ float g_f0n [MAXN * 128];       // [s, |v|]
__device__ float g_t1  [MAXN * 128];
__device__ float g_g   [MAXN * 128];       // norm_gate MLP out
__device__ float g_hvg [3 * MAXN * 64];    // gated vectors
__device__ float g_na0s[MAXN * 64];
__device__ float g_na0v[3 * MAXN * 64];
__device__ float g_hs  [MAXN * 64];
__device__ float g_hv  [3 * MAXN * 64];
// edge side
__device__ float g_s0  [(size_t)MAXE * 192];
__device__ float g_t8  [(size_t)MAXE * 8];
__device__ float g_u   [(size_t)MAXE * 64];
__device__ float g_fe  [(size_t)MAXE * 320];
__device__ float g_w   [(size_t)MAXE * 320];
__device__ float g_f0e [(size_t)MAXE * 128];
__device__ float g_pv  [3 * (size_t)MAXE * 64];
__device__ float g_t2  [(size_t)MAXE * 128];
__device__ float g_g2  [(size_t)MAXE * 128];
__device__ float g_vg  [3 * (size_t)MAXE * 64];

__device__ __forceinline__ float siluf(float x) { return x * (1.f / (1.f + __expf(-x))); }
__device__ __forceinline__ float sspf(float x) {
    float sp = (x > 20.f) ? x : log1pf(__expf(x));
    return sp - 0.6931471805599453f;
}

// packed fp32x2 FMA (sm_103a)
#define FFMA2(d, a, b) asm("fma.rn.f32x2 %0, %1, %2, %0;" : "+l"(d) : "l"(a), "l"(b))

// ---------------- generic tiled GEMM ----------------
// C[row, n] = epilogue( alpha * sum_k A[row,k] * W[k,n] )
// block tile: 128 rows x 64 cols, BK=32. 256 threads, thread tile 8x4 via f32x2 pairs.
#define BM 128
#define BN 64
#define BK 32
#define AS_LD 132   // padded, 16B-aligned rows
#define WS_LD 136   // duplicated-pair weight rows, 16B-aligned

__global__ void __launch_bounds__(256) gemm_kernel(
    const float* __restrict__ A, int lda, size_t aPlane,
    const float* __restrict__ W, int ldw,
    const float* __restrict__ bias,
    const float* __restrict__ aux, int auxLd, float auxScale,
    const float* __restrict__ res,
    float* __restrict__ out, int outLd, int colStride, int colOff, int zColStep, size_t outPlane,
    int M, int K, float alpha, int act)
{
    __shared__ __align__(16) float As[BK * AS_LD];
    __shared__ __align__(16) float WsD[BK * WS_LD];

    const int z = blockIdx.z;
    A += (size_t)z * aPlane;
    out += (size_t)z * outPlane;
    const int cOff = colOff + z * zColStep;

    const int tid = threadIdx.x;
    const int tx = tid & 15;       // col group: 4 cols
    const int ty = tid >> 4;       // row group: 8 rows
    const int wid = tid >> 5, lane = tid & 31;
    const int rowBase = blockIdx.x * BM;
    const int nBase = blockIdx.y * BN;

    unsigned long long acc[4][4];
#pragma unroll
    for (int p = 0; p < 4; p++)
#pragma unroll
        for (int c = 0; c < 4; c++) acc[p][c] = 0ull;

    for (int k0 = 0; k0 < K; k0 += BK) {
        // fill A tile: As[k][m], warp wid loads 16 rows, lane = k
#pragma unroll 4
        for (int r = 0; r < 16; r++) {
            int mLoc = wid * 16 + r;
            int gRow = rowBase + mLoc;
            float v = 0.f;
            if (gRow < M) v = A[(size_t)gRow * lda + k0 + lane];
            As[lane * AS_LD + mLoc] = v;
        }
        // fill duplicated W tile
        for (int i = tid; i < BK * BN; i += 256) {
            int k = i >> 6, n = i & 63;
            float wv = W[(size_t)(k0 + k) * ldw + nBase + n];
            int o = k * WS_LD + 2 * n;
            WsD[o] = wv; WsD[o + 1] = wv;
        }
        __syncthreads();

#pragma unroll
        for (int k = 0; k < BK; k++) {
            const ulonglong2* ap = (const ulonglong2*)&As[k * AS_LD + ty * 8];
            ulonglong2 a0 = ap[0], a1 = ap[1];                 // row pairs (0,1)(2,3)(4,5)(6,7)
            const ulonglong2* wp = (const ulonglong2*)&WsD[k * WS_LD + tx * 8];
            ulonglong2 w0 = wp[0], w1 = wp[1];                 // dup cols c0,c1,c2,c3
            FFMA2(acc[0][0], a0.x, w0.x); FFMA2(acc[0][1], a0.x, w0.y);
            FFMA2(acc[0][2], a0.x, w1.x); FFMA2(acc[0][3], a0.x, w1.y);
            FFMA2(acc[1][0], a0.y, w0.x); FFMA2(acc[1][1], a0.y, w0.y);
            FFMA2(acc[1][2], a0.y, w1.x); FFMA2(acc[1][3], a0.y, w1.y);
            FFMA2(acc[2][0], a1.x, w0.x); FFMA2(acc[2][1], a1.x, w0.y);
            FFMA2(acc[2][2], a1.x, w1.x); FFMA2(acc[2][3], a1.x, w1.y);
            FFMA2(acc[3][0], a1.y, w0.x); FFMA2(acc[3][1], a1.y, w0.y);
            FFMA2(acc[3][2], a1.y, w1.x); FFMA2(acc[3][3], a1.y, w1.y);
        }
        __syncthreads();
    }

    // epilogue
#pragma unroll
    for (int p = 0; p < 4; p++) {
#pragma unroll
        for (int h = 0; h < 2; h++) {
            int row = rowBase + ty * 8 + 2 * p + h;
            if (row >= M) continue;
#pragma unroll
            for (int c = 0; c < 4; c++) {
                unsigned long long uacc = acc[p][c];
                float v = __uint_as_float(h == 0 ? (unsigned)uacc : (unsigned)(uacc >> 32));
                v *= alpha;
                int nG = nBase + tx * 4 + c;
                if (bias) v += bias[nG];
                if (act == 1) v = siluf(v);
                if (aux) v *= aux[(size_t)row * auxLd + nG] * auxScale;
                size_t oi = (size_t)row * outLd + cOff + (size_t)nG * colStride;
                if (res) v += res[oi];
                out[oi] = v;
            }
        }
    }
}

// ---------------- elementwise / gather kernels ----------------

__global__ void prep_node_kernel(const float* __restrict__ na, int N) {
    int idx = blockIdx.x * blockDim.x + threadIdx.x;
    int n = idx >> 6, j = idx & 63;
    if (n >= N) return;
    const float* b = na + (size_t)n * 256;
    float s = b[j];
    g_sn[n * 64 + j] = s;
    g_f0n[n * 128 + j] = s;
    float nn = 0.f;
#pragma unroll
    for (int c = 0; c < 3; c++) {
        float x = b[64 + 3 * j + c];
        g_xv[(size_t)c * NPLANE + n * 64 + j] = x;
        nn += x * x;
    }
    g_f0n[n * 128 + 64 + j] = sqrtf(nn);
}

__global__ void gate_node_kernel(int N) {
    int idx = blockIdx.x * blockDim.x + threadIdx.x;
    int n = idx >> 6, j = idx & 63;
    if (n >= N) return;
    float ga = g_g[n * 128 + 64 + j];
#pragma unroll
    for (int c = 0; c < 3; c++)
        g_hvg[(size_t)c * NPLANE + n * 64 + j] = g_xv[(size_t)c * NPLANE + n * 64 + j] * ga;
}

// s0 = [na0_s[dst], na0_s[src], ip/3]; t8 = ssp(edge_attr @ feW1 / sqrt(32))
__global__ void gather_kernel(const float* __restrict__ ea, const int* __restrict__ ei,
                              const float* __restrict__ feW1, int E) {
    int idx = blockIdx.x * blockDim.x + threadIdx.x;
    int e = idx >> 6, j = idx & 63;
    if (e >= E) return;
    int dst = ei[e], src = ei[E + e];
    g_s0[(size_t)e * 192 + j] = g_na0s[dst * 64 + j];
    g_s0[(size_t)e * 192 + 64 + j] = g_na0s[src * 64 + j];
    float ip = 0.f;
#pragma unroll
    for (int c = 0; c < 3; c++)
        ip += g_na0v[(size_t)c * NPLANE + dst * 64 + j] * g_na0v[(size_t)c * NPLANE + src * 64 + j];
    g_s0[(size_t)e * 192 + 128 + j] = ip * (1.f / 3.f);
    if (j < 8) {
        float a = 0.f;
        const float* er = ea + (size_t)e * 32;
#pragma unroll 8
        for (int k = 0; k < 32; k++) a += er[k] * feW1[k * 8 + j];
        g_t8[(size_t)e * 8 + j] = sspf(a * 0.17677669529663687f);
    }
}

// fe = t8 @ feW2 (unscaled; scale folded into Q3 auxScale)
__global__ void fe_kernel(const float* __restrict__ feW2, int E) {
    int idx = blockIdx.x * blockDim.x + threadIdx.x;
    int e = idx / 80, q = idx % 80;
    if (e >= E) return;
    float t[8];
#pragma unroll
    for (int i = 0; i < 8; i++) t[i] = g_t8[(size_t)e * 8 + i];
    int n0 = q * 4;
    float4 acc = make_float4(0.f, 0.f, 0.f, 0.f);
#pragma unroll
    for (int i = 0; i < 8; i++) {
        float4 wv = *(const float4*)&feW2[i * 320 + n0];
        acc.x += t[i] * wv.x; acc.y += t[i] * wv.y; acc.z += t[i] * wv.z; acc.w += t[i] * wv.w;
    }
    *(float4*)&g_fe[(size_t)e * 320 + n0] = acc;
}

// tensor product: f0e = [pair_s, |pair_v|], pv planes
__global__ void tp_kernel(const int* __restrict__ ei, int E) {
    int idx = blockIdx.x * blockDim.x + threadIdx.x;
    int e = idx >> 4, t = idx & 15;
    if (e >= E) return;
    int dst = ei[e], src = ei[E + e];
    const float C0 = 0.4472135954999579f, C1 = 0.7745966692414834f;
    const float IS3 = 0.5773502691896258f, IS6 = 0.4082482904638630f;
    const float* we = g_w + (size_t)e * 320;
#pragma unroll
    for (int k = 0; k < 4; k++) {
        int i = 4 * t + k;
        float xs = g_hs[src * 64 + i], ys = g_hs[dst * 64 + i];
        float xv0 = g_hv[0 * NPLANE + src * 64 + i], yv0 = g_hv[0 * NPLANE + dst * 64 + i];
        float xv1 = g_hv[1 * NPLANE + src * 64 + i], yv1 = g_hv[1 * NPLANE + dst * 64 + i];
        float xv2 = g_hv[2 * NPLANE + src * 64 + i], yv2 = g_hv[2 * NPLANE + dst * 64 + i];
        float ipv = xv0 * yv0 + xv1 * yv1 + xv2 * yv2;
        float psv = C0 * (we[i] * xs * ys + we[192 + i] * ipv * IS3);
        float cx = xv1 * yv2 - xv2 * yv1;
        float cy = xv2 * yv0 - xv0 * yv2;
        float cz = xv0 * yv1 - xv1 * yv0;
        float a011 = we[64 + i] * IS3 * C1;
        float a101 = we[128 + i] * IS3 * C1;
        float a111 = we[256 + i] * IS6 * C1;
        float p0 = a011 * xs * yv0 + a101 * xv0 * ys + a111 * cx;
        float p1 = a011 * xs * yv1 + a101 * xv1 * ys + a111 * cy;
        float p2 = a011 * xs * yv2 + a101 * xv2 * ys + a111 * cz;
        g_pv[0 * EPLANE + (size_t)e * 64 + i] = p0;
        g_pv[1 * EPLANE + (size_t)e * 64 + i] = p1;
        g_pv[2 * EPLANE + (size_t)e * 64 + i] = p2;
        g_f0e[(size_t)e * 128 + i] = psv;
        g_f0e[(size_t)e * 128 + 64 + i] = sqrtf(p0 * p0 + p1 * p1 + p2 * p2);
    }
}

__global__ void gate_edge_kernel(int E) {
    int idx = blockIdx.x * blockDim.x + threadIdx.x;
    int e = idx >> 6, j = idx & 63;
    if (e >= E) return;
    float ga = g_g2[(size_t)e * 128 + 64 + j];
#pragma unroll
    for (int c = 0; c < 3; c++)
        g_vg[(size_t)c * EPLANE + (size_t)e * 64 + j] = g_pv[(size_t)c * EPLANE + (size_t)e * 64 + j] * ga;
}

// ---------------- host ----------------

static void launch_gemm(const float* A, int lda, size_t aPlane,
                        const float* W, int ldw, const float* bias,
                        const float* aux, int auxLd, float auxScale,
                        const float* res,
                        float* out, int outLd, int colStride, int colOff, int zColStep, size_t outPlane,
                        int M, int K, int N, int planes, float alpha, int act)
{
    dim3 grid((M + BM - 1) / BM, N / BN, planes);
    gemm_kernel<<<grid, 256>>>(A, lda, aPlane, W, ldw, bias, aux, auxLd, auxScale, res,
                               out, outLd, colStride, colOff, zColStep, outPlane, M, K, alpha, act);
}

extern "C" void kernel_launch(void* const* d_in, const int* in_sizes, int n_in,
                              void* d_out, int out_size)
{
    const float* node_attr = (const float*)d_in[0];
    const float* edge_attr = (const float*)d_in[1];
    const float* npa       = (const float*)d_in[2];
    const float* Wi0 = (const float*)d_in[3];
    const float* bi0 = (const float*)d_in[4];
    const float* Wi1 = (const float*)d_in[5];
    const float* gpW1 = (const float*)d_in[6];
    const float* gpb1 = (const float*)d_in[7];
    const float* gpW2 = (const float*)d_in[8];
    const float* gpb2 = (const float*)d_in[9];
    const float* Wn0 = (const float*)d_in[10];
    const float* bn0 = (const float*)d_in[11];
    const float* Wn1 = (const float*)d_in[12];
    const float* feW1 = (const float*)d_in[13];
    const float* feW2 = (const float*)d_in[14];
    const float* fsW1 = (const float*)d_in[15];
    const float* fsb1 = (const float*)d_in[16];
    const float* fsW2 = (const float*)d_in[17];
    const float* fsb2 = (const float*)d_in[18];
    const float* gW1 = (const float*)d_in[19];
    const float* gb1 = (const float*)d_in[20];
    const float* gW2 = (const float*)d_in[21];
    const float* gb2 = (const float*)d_in[22];
    const float* Wo0 = (const float*)d_in[23];
    const float* bo0 = (const float*)d_in[24];
    const float* Wo1 = (const float*)d_in[25];
    const int*   ei  = (const int*)d_in[26];

    int N = in_sizes[0] / 256; if (N > MAXN) N = MAXN;
    int E = in_sizes[26] / 2;  if (E > MAXE) E = MAXE;
    float* out = (float*)d_out;

    float *sn, *xv, *f0n, *t1, *gg, *hvg, *na0s, *na0v, *hs, *hv;
    float *s0, *u, *fe, *w, *f0e, *pv, *t2, *g2, *vg;
    cudaGetSymbolAddress((void**)&sn, g_sn);   cudaGetSymbolAddress((void**)&xv, g_xv);
    cudaGetSymbolAddress((void**)&f0n, g_f0n); cudaGetSymbolAddress((void**)&t1, g_t1);
    cudaGetSymbolAddress((void**)&gg, g_g);    cudaGetSymbolAddress((void**)&hvg, g_hvg);
    cudaGetSymbolAddress((void**)&na0s, g_na0s); cudaGetSymbolAddress((void**)&na0v, g_na0v);
    cudaGetSymbolAddress((void**)&hs, g_hs);   cudaGetSymbolAddress((void**)&hv, g_hv);
    cudaGetSymbolAddress((void**)&s0, g_s0);   cudaGetSymbolAddress((void**)&u, g_u);
    cudaGetSymbolAddress((void**)&fe, g_fe);   cudaGetSymbolAddress((void**)&w, g_w);
    cudaGetSymbolAddress((void**)&f0e, g_f0e); cudaGetSymbolAddress((void**)&pv, g_pv);
    cudaGetSymbolAddress((void**)&t2, g_t2);   cudaGetSymbolAddress((void**)&g2, g_g2);
    cudaGetSymbolAddress((void**)&vg, g_vg);

    const float ISQ8 = 0.3535533905932738f;

    // ---- node pipeline ----
    prep_node_kernel<<<(N * 64 + 255) / 256, 256>>>(node_attr, N);
    launch_gemm(sn, 64, 0, Wi0, 64, bi0, 0, 0, 0.f, 0,
                na0s, 64, 1, 0, 0, 0, N, 64, 64, 1, 0.125f, 0);
    launch_gemm(xv, 64, NPLANE, Wi1, 64, 0, 0, 0, 0.f, 0,
                na0v, 64, 1, 0, 0, NPLANE, N, 64, 64, 3, 0.125f, 0);
    launch_gemm(f0n, 128, 0, gpW1, 128, gpb1, 0, 0, 0.f, 0,
                t1, 128, 1, 0, 0, 0, N, 128, 128, 1, 1.f, 1);
    launch_gemm(t1, 128, 0, gpW2, 128, gpb2, 0, 0, 0.f, 0,
                gg, 128, 1, 0, 0, 0, N, 128, 128, 1, 1.f, 0);
    gate_node_kernel<<<(N * 64 + 255) / 256, 256>>>(N);
    launch_gemm(gg, 128, 0, Wn0, 64, bn0, 0, 0, 0.f, 0,
                hs, 64, 1, 0, 0, 0, N, 64, 64, 1, 0.125f, 0);
    launch_gemm(hvg, 64, NPLANE, Wn1, 64, 0, 0, 0, 0.f, 0,
                hv, 64, 1, 0, 0, NPLANE, N, 64, 64, 3, 0.125f, 0);

    // ---- edge pipeline ----
    gather_kernel<<<(E * 64 + 255) / 256, 256>>>(edge_attr, ei, feW1, E);
    launch_gemm(s0, 192, 0, fsW1, 64, fsb1, 0, 0, 0.f, 0,
                u, 64, 1, 0, 0, 0, E, 192, 64, 1, 1.f, 1);
    fe_kernel<<<(E * 80 + 255) / 256, 256>>>(feW2, E);
    launch_gemm(u, 64, 0, fsW2, 320, fsb2, fe, 320, ISQ8, 0,
                w, 320, 1, 0, 0, 0, E, 64, 320, 1, 1.f, 0);
    tp_kernel<<<(E * 16 + 255) / 256, 256>>>(ei, E);
    launch_gemm(f0e, 128, 0, gW1, 128, gb1, 0, 0, 0.f, 0,
                t2, 128, 1, 0, 0, 0, E, 128, 128, 1, 1.f, 1);
    launch_gemm(t2, 128, 0, gW2, 128, gb2, 0, 0, 0.f, 0,
                g2, 128, 1, 0, 0, 0, E, 128, 128, 1, 1.f, 0);
    gate_edge_kernel<<<(E * 64 + 255) / 256, 256>>>(E);
    // out scalars: cols 0..63
    launch_gemm(g2, 128, 0, Wo0, 64, bo0, 0, 0, 0.f, npa,
                out, 256, 1, 0, 0, 0, E, 64, 64, 1, 0.125f, 0);
    // out vectors: cols 64 + 3n + z
    launch_gemm(vg, 64, EPLANE, Wo1, 64, 0, 0, 0, 0.f, npa,
                out, 256, 3, 64, 1, 0, E, 64, 64, 3, 0.125f, 0);
}

// round 10
// speedup vs baseline: 1.5144x; 1.0062x over previous
#include <cuda_runtime.h>
#include <math.h>

#define MAXN 20480
#define MAXE 122880
#define NPLANE ((size_t)MAXN * 64)
#define EPLANE ((size_t)MAXE * 64)

// ---------------- scratch (__device__, static) ----------------
__device__ float g_sn  [MAXN * 64];
__device__ float g_xv  [3 * MAXN * 64];
__device__ float g_f0n [MAXN * 128];
__device__ float g_t1  [MAXN * 128];
__device__ float g_g   [MAXN * 128];
__device__ float g_na0s[MAXN * 64];
__device__ float g_na0v[3 * MAXN * 64];
__device__ float g_hs  [MAXN * 64];
__device__ float g_hv  [3 * MAXN * 64];
__device__ float g_s0  [(size_t)MAXE * 192];
__device__ float g_t8  [(size_t)MAXE * 8];
__device__ float g_u   [(size_t)MAXE * 64];
__device__ float g_w   [(size_t)MAXE * 320];
__device__ float g_f0e [(size_t)MAXE * 128];
__device__ float g_pv  [3 * (size_t)MAXE * 64];
__device__ float g_t2  [(size_t)MAXE * 128];
__device__ float g_g2  [(size_t)MAXE * 128];

__device__ __forceinline__ float siluf(float x) { return x * (1.f / (1.f + __expf(-x))); }
__device__ __forceinline__ float sspf(float x) {
    float sp = (x > 20.f) ? x : log1pf(__expf(x));
    return sp - 0.6931471805599453f;
}

#define FFMA2(d, a, b) asm("fma.rn.f32x2 %0, %1, %2, %0;" : "+l"(d) : "l"(a), "l"(b))

// ---------------- pipelined tiled GEMM ----------------
#define BM 128
#define BN 64
#define BK 32
#define AS_LD 132
#define WS_LD 136

__global__ void __launch_bounds__(256) gemm_kernel(
    const float* __restrict__ A, int lda, size_t aPlane,
    const float* __restrict__ gateP, int gateLd,
    const float* __restrict__ W, int ldw,
    const float* __restrict__ bias,
    const float* __restrict__ aux, int auxLd, float auxScale,
    const float* __restrict__ t8p, const float* __restrict__ feW2p,
    const float* __restrict__ res,
    float* __restrict__ out, int outLd, int colStride, int colOff, int zColStep, size_t outPlane,
    int M, int K, float alpha, int act)
{
    __shared__ __align__(16) float As[2][BK * AS_LD];
    __shared__ __align__(16) float WsD[2][BK * WS_LD];

    const int z = blockIdx.z;
    A += (size_t)z * aPlane;
    out += (size_t)z * outPlane;
    const int cOff = colOff + z * zColStep;

    const int tid = threadIdx.x;
    const int tx = tid & 15, ty = tid >> 4;
    const int rowBase = blockIdx.x * BM;
    const int nBase = blockIdx.y * BN;

    float4 aBuf[4], wBuf[2];

    auto fillRegs = [&](int k0) {
#pragma unroll
        for (int ld = 0; ld < 4; ld++) {
            int idx = ld * 256 + tid;
            int r = idx >> 3, kq = idx & 7;
            int gRow = rowBase + r;
            float4 v = make_float4(0.f, 0.f, 0.f, 0.f);
            if (gRow < M) {
                v = *(const float4*)&A[(size_t)gRow * lda + k0 + kq * 4];
                if (gateP) {
                    const float* gp = &gateP[(size_t)gRow * gateLd + k0 + kq * 4];
                    v.x *= gp[0]; v.y *= gp[1]; v.z *= gp[2]; v.w *= gp[3];
                }
            }
            aBuf[ld] = v;
        }
#pragma unroll
        for (int ld = 0; ld < 2; ld++) {
            int idx = ld * 256 + tid;
            int k = idx >> 4, nq = idx & 15;
            wBuf[ld] = *(const float4*)&W[(size_t)(k0 + k) * ldw + nBase + nq * 4];
        }
    };
    auto storeSmem = [&](int buf) {
#pragma unroll
        for (int ld = 0; ld < 4; ld++) {
            int idx = ld * 256 + tid;
            int r = idx >> 3, kq = idx & 7;
            float* ap = &As[buf][(kq * 4) * AS_LD + r];
            ap[0 * AS_LD] = aBuf[ld].x;
            ap[1 * AS_LD] = aBuf[ld].y;
            ap[2 * AS_LD] = aBuf[ld].z;
            ap[3 * AS_LD] = aBuf[ld].w;
        }
#pragma unroll
        for (int ld = 0; ld < 2; ld++) {
            int idx = ld * 256 + tid;
            int k = idx >> 4, nq = idx & 15;
            float2* wp = (float2*)&WsD[buf][k * WS_LD + 8 * nq];
            wp[0] = make_float2(wBuf[ld].x, wBuf[ld].x);
            wp[1] = make_float2(wBuf[ld].y, wBuf[ld].y);
            wp[2] = make_float2(wBuf[ld].z, wBuf[ld].z);
            wp[3] = make_float2(wBuf[ld].w, wBuf[ld].w);
        }
    };

    unsigned long long acc[4][4];
#pragma unroll
    for (int p = 0; p < 4; p++)
#pragma unroll
        for (int c = 0; c < 4; c++) acc[p][c] = 0ull;

    const int tiles = K / BK;
    fillRegs(0);
    storeSmem(0);
    __syncthreads();

    for (int t = 0; t < tiles; t++) {
        const int cur = t & 1;
        if (t + 1 < tiles) fillRegs((t + 1) * BK);
#pragma unroll
        for (int k = 0; k < BK; k++) {
            const ulonglong2* ap = (const ulonglong2*)&As[cur][k * AS_LD + ty * 8];
            ulonglong2 a0 = ap[0], a1 = ap[1];
            const ulonglong2* wp = (const ulonglong2*)&WsD[cur][k * WS_LD + tx * 8];
            ulonglong2 w0 = wp[0], w1 = wp[1];
            FFMA2(acc[0][0], a0.x, w0.x); FFMA2(acc[0][1], a0.x, w0.y);
            FFMA2(acc[0][2], a0.x, w1.x); FFMA2(acc[0][3], a0.x, w1.y);
            FFMA2(acc[1][0], a0.y, w0.x); FFMA2(acc[1][1], a0.y, w0.y);
            FFMA2(acc[1][2], a0.y, w1.x); FFMA2(acc[1][3], a0.y, w1.y);
            FFMA2(acc[2][0], a1.x, w0.x); FFMA2(acc[2][1], a1.x, w0.y);
            FFMA2(acc[2][2], a1.x, w1.x); FFMA2(acc[2][3], a1.x, w1.y);
            FFMA2(acc[3][0], a1.y, w0.x); FFMA2(acc[3][1], a1.y, w0.y);
            FFMA2(acc[3][2], a1.y, w1.x); FFMA2(acc[3][3], a1.y, w1.y);
        }
        if (t + 1 < tiles) storeSmem(cur ^ 1);
        __syncthreads();
    }

#pragma unroll
    for (int p = 0; p < 4; p++) {
#pragma unroll
        for (int h = 0; h < 2; h++) {
            int row = rowBase + ty * 8 + 2 * p + h;
            if (row >= M) continue;
            float t8row[8];
            if (t8p) {
#pragma unroll
                for (int i = 0; i < 8; i++) t8row[i] = t8p[(size_t)row * 8 + i];
            }
#pragma unroll
            for (int c = 0; c < 4; c++) {
                unsigned long long uacc = acc[p][c];
                float v = __uint_as_float(h == 0 ? (unsigned)uacc : (unsigned)(uacc >> 32));
                v *= alpha;
                int nG = nBase + tx * 4 + c;
                if (bias) v += bias[nG];
                if (act == 1) v = siluf(v);
                if (aux) v *= aux[(size_t)row * auxLd + nG] * auxScale;
                else if (t8p) {
                    float s = 0.f;
#pragma unroll
                    for (int i = 0; i < 8; i++) s += t8row[i] * feW2p[i * 320 + nG];
                    v *= s * auxScale;
                }
                size_t oi = (size_t)row * outLd + cOff + (size_t)nG * colStride;
                if (res) v += res[oi];
                out[oi] = v;
            }
        }
    }
}

// ---------------- elementwise / gather kernels ----------------

__global__ void prep_node_kernel(const float* __restrict__ na, int N) {
    int idx = blockIdx.x * blockDim.x + threadIdx.x;
    int n = idx >> 6, j = idx & 63;
    if (n >= N) return;
    const float* b = na + (size_t)n * 256;
    float s = b[j];
    g_sn[n * 64 + j] = s;
    g_f0n[n * 128 + j] = s;
    float nn = 0.f;
#pragma unroll
    for (int c = 0; c < 3; c++) {
        float x = b[64 + 3 * j + c];
        g_xv[(size_t)c * NPLANE + n * 64 + j] = x;
        nn += x * x;
    }
    g_f0n[n * 128 + 64 + j] = sqrtf(nn);
}

__global__ void gather_kernel(const float* __restrict__ ea, const int* __restrict__ ei,
                              const float* __restrict__ feW1, int E) {
    int idx = blockIdx.x * blockDim.x + threadIdx.x;
    int e = idx >> 6, j = idx & 63;
    if (e >= E) return;
    int dst = ei[e], src = ei[E + e];
    g_s0[(size_t)e * 192 + j] = g_na0s[dst * 64 + j];
    g_s0[(size_t)e * 192 + 64 + j] = g_na0s[src * 64 + j];
    float ip = 0.f;
#pragma unroll
    for (int c = 0; c < 3; c++)
        ip += g_na0v[(size_t)c * NPLANE + dst * 64 + j] * g_na0v[(size_t)c * NPLANE + src * 64 + j];
    g_s0[(size_t)e * 192 + 128 + j] = ip * (1.f / 3.f);
    if (j < 8) {
        float a = 0.f;
        const float* er = ea + (size_t)e * 32;
#pragma unroll 8
        for (int k = 0; k < 32; k++) a += er[k] * feW1[k * 8 + j];
        g_t8[(size_t)e * 8 + j] = sspf(a * 0.17677669529663687f);
    }
}

__global__ void tp_kernel(const int* __restrict__ ei, int E) {
    int idx = blockIdx.x * blockDim.x + threadIdx.x;
    int e = idx >> 4, t = idx & 15;
    if (e >= E) return;
    int dst = ei[e], src = ei[E + e];
    const float C0 = 0.4472135954999579f, C1 = 0.7745966692414834f;
    const float IS3 = 0.5773502691896258f, IS6 = 0.4082482904638630f;
    const float* we = g_w + (size_t)e * 320;
#pragma unroll
    for (int k = 0; k < 4; k++) {
        int i = 4 * t + k;
        float xs = g_hs[src * 64 + i], ys = g_hs[dst * 64 + i];
        float xv0 = g_hv[0 * NPLANE + src * 64 + i], yv0 = g_hv[0 * NPLANE + dst * 64 + i];
        float xv1 = g_hv[1 * NPLANE + src * 64 + i], yv1 = g_hv[1 * NPLANE + dst * 64 + i];
        float xv2 = g_hv[2 * NPLANE + src * 64 + i], yv2 = g_hv[2 * NPLANE + dst * 64 + i];
        float ipv = xv0 * yv0 + xv1 * yv1 + xv2 * yv2;
        float psv = C0 * (we[i] * xs * ys + we[192 + i] * ipv * IS3);
        float cx = xv1 * yv2 - xv2 * yv1;
        float cy = xv2 * yv0 - xv0 * yv2;
        float cz = xv0 * yv1 - xv1 * yv0;
        float a011 = we[64 + i] * IS3 * C1;
        float a101 = we[128 + i] * IS3 * C1;
        float a111 = we[256 + i] * IS6 * C1;
        float p0 = a011 * xs * yv0 + a101 * xv0 * ys + a111 * cx;
        float p1 = a011 * xs * yv1 + a101 * xv1 * ys + a111 * cy;
        float p2 = a011 * xs * yv2 + a101 * xv2 * ys + a111 * cz;
        g_pv[0 * EPLANE + (size_t)e * 64 + i] = p0;
        g_pv[1 * EPLANE + (size_t)e * 64 + i] = p1;
        g_pv[2 * EPLANE + (size_t)e * 64 + i] = p2;
        g_f0e[(size_t)e * 128 + i] = psv;
        g_f0e[(size_t)e * 128 + 64 + i] = sqrtf(p0 * p0 + p1 * p1 + p2 * p2);
    }
}

// ---------------- host ----------------

static void launch_gemm(const float* A, int lda, size_t aPlane,
                        const float* gateP, int gateLd,
                        const float* W, int ldw, const float* bias,
                        const float* aux, int auxLd, float auxScale,
                        const float* t8p, const float* feW2p,
                        const float* res,
                        float* out, int outLd, int colStride, int colOff, int zColStep, size_t outPlane,
                        int M, int K, int N, int planes, float alpha, int act)
{
    dim3 grid((M + BM - 1) / BM, N / BN, planes);
    gemm_kernel<<<grid, 256>>>(A, lda, aPlane, gateP, gateLd, W, ldw, bias,
                               aux, auxLd, auxScale, t8p, feW2p, res,
                               out, outLd, colStride, colOff, zColStep, outPlane, M, K, alpha, act);
}

extern "C" void kernel_launch(void* const* d_in, const int* in_sizes, int n_in,
                              void* d_out, int out_size)
{
    const float* node_attr = (const float*)d_in[0];
    const float* edge_attr = (const float*)d_in[1];
    const float* npa       = (const float*)d_in[2];
    const float* Wi0 = (const float*)d_in[3];
    const float* bi0 = (const float*)d_in[4];
    const float* Wi1 = (const float*)d_in[5];
    const float* gpW1 = (const float*)d_in[6];
    const float* gpb1 = (const float*)d_in[7];
    const float* gpW2 = (const float*)d_in[8];
    const float* gpb2 = (const float*)d_in[9];
    const float* Wn0 = (const float*)d_in[10];
    const float* bn0 = (const float*)d_in[11];
    const float* Wn1 = (const float*)d_in[12];
    const float* feW1 = (const float*)d_in[13];
    const float* feW2 = (const float*)d_in[14];
    const float* fsW1 = (const float*)d_in[15];
    const float* fsb1 = (const float*)d_in[16];
    const float* fsW2 = (const float*)d_in[17];
    const float* fsb2 = (const float*)d_in[18];
    const float* gW1 = (const float*)d_in[19];
    const float* gb1 = (const float*)d_in[20];
    const float* gW2 = (const float*)d_in[21];
    const float* gb2 = (const float*)d_in[22];
    const float* Wo0 = (const float*)d_in[23];
    const float* bo0 = (const float*)d_in[24];
    const float* Wo1 = (const float*)d_in[25];
    const int*   ei  = (const int*)d_in[26];

    int N = in_sizes[0] / 256; if (N > MAXN) N = MAXN;
    int E = in_sizes[26] / 2;  if (E > MAXE) E = MAXE;
    float* out = (float*)d_out;

    float *sn, *xv, *f0n, *t1, *gg, *na0s, *na0v, *hs, *hv;
    float *s0, *u, *t8, *w, *f0e, *pv, *t2, *g2;
    cudaGetSymbolAddress((void**)&sn, g_sn);   cudaGetSymbolAddress((void**)&xv, g_xv);
    cudaGetSymbolAddress((void**)&f0n, g_f0n); cudaGetSymbolAddress((void**)&t1, g_t1);
    cudaGetSymbolAddress((void**)&gg, g_g);
    cudaGetSymbolAddress((void**)&na0s, g_na0s); cudaGetSymbolAddress((void**)&na0v, g_na0v);
    cudaGetSymbolAddress((void**)&hs, g_hs);   cudaGetSymbolAddress((void**)&hv, g_hv);
    cudaGetSymbolAddress((void**)&s0, g_s0);   cudaGetSymbolAddress((void**)&u, g_u);
    cudaGetSymbolAddress((void**)&t8, g_t8);   cudaGetSymbolAddress((void**)&w, g_w);
    cudaGetSymbolAddress((void**)&f0e, g_f0e); cudaGetSymbolAddress((void**)&pv, g_pv);
    cudaGetSymbolAddress((void**)&t2, g_t2);   cudaGetSymbolAddress((void**)&g2, g_g2);

    const float ISQ8 = 0.3535533905932738f;

    // ---- node pipeline ----
    prep_node_kernel<<<(N * 64 + 255) / 256, 256>>>(node_attr, N);
    launch_gemm(sn, 64, 0, 0, 0, Wi0, 64, bi0, 0, 0, 0.f, 0, 0, 0,
                na0s, 64, 1, 0, 0, 0, N, 64, 64, 1, 0.125f, 0);
    launch_gemm(xv, 64, NPLANE, 0, 0, Wi1, 64, 0, 0, 0, 0.f, 0, 0, 0,
                na0v, 64, 1, 0, 0, NPLANE, N, 64, 64, 3, 0.125f, 0);
    launch_gemm(f0n, 128, 0, 0, 0, gpW1, 128, gpb1, 0, 0, 0.f, 0, 0, 0,
                t1, 128, 1, 0, 0, 0, N, 128, 128, 1, 1.f, 1);
    launch_gemm(t1, 128, 0, 0, 0, gpW2, 128, gpb2, 0, 0, 0.f, 0, 0, 0,
                gg, 128, 1, 0, 0, 0, N, 128, 128, 1, 1.f, 0);
    launch_gemm(gg, 128, 0, 0, 0, Wn0, 64, bn0, 0, 0, 0.f, 0, 0, 0,
                hs, 64, 1, 0, 0, 0, N, 64, 64, 1, 0.125f, 0);
    launch_gemm(xv, 64, NPLANE, gg + 64, 128, Wn1, 64, 0, 0, 0, 0.f, 0, 0, 0,
                hv, 64, 1, 0, 0, NPLANE, N, 64, 64, 3, 0.125f, 0);

    // ---- edge pipeline ----
    gather_kernel<<<(E * 64 + 255) / 256, 256>>>(edge_attr, ei, feW1, E);
    launch_gemm(s0, 192, 0, 0, 0, fsW1, 64, fsb1, 0, 0, 0.f, 0, 0, 0,
                u, 64, 1, 0, 0, 0, E, 192, 64, 1, 1.f, 1);
    launch_gemm(u, 64, 0, 0, 0, fsW2, 320, fsb2, 0, 0, ISQ8, t8, feW2, 0,
                w, 320, 1, 0, 0, 0, E, 64, 320, 1, 1.f, 0);
    tp_kernel<<<(E * 16 + 255) / 256, 256>>>(ei, E);
    launch_gemm(f0e, 128, 0, 0, 0, gW1, 128, gb1, 0, 0, 0.f, 0, 0, 0,
                t2, 128, 1, 0, 0, 0, E, 128, 128, 1, 1.f, 1);
    launch_gemm(t2, 128, 0, 0, 0, gW2, 128, gb2, 0, 0, 0.f, 0, 0, 0,
                g2, 128, 1, 0, 0, 0, E, 128, 128, 1, 1.f, 0);
    launch_gemm(g2, 128, 0, 0, 0, Wo0, 64, bo0, 0, 0, 0.f, 0, 0, npa,
                out, 256, 1, 0, 0, 0, E, 64, 64, 1, 0.125f, 0);
    launch_gemm(pv, 64, EPLANE, g2 + 64, 128, Wo1, 64, 0, 0, 0, 0.f, 0, 0, npa,
                out, 256, 3, 64, 1, 0, E, 64, 64, 3, 0.125f, 0);
}